// round 4
// baseline (speedup 1.0000x reference)
#include <cuda_runtime.h>
#include <cuda_bf16.h>

// Problem constants (fixed by the dataset)
#define Bn 4
#define Nn 50000
#define Dn 256
#define En 800000
#define NPTS (Bn * Nn)   // 200000

// XPBD state, node-major packed: node n owns 12 floats (4 batches x xyz):
//   [12n+0..2]=b0, [12n+3..5]=b1, [12n+6..8]=b2, [12n+9..11]=b3
// = 3 float4s per node. Ping-pong buffers; node-centric update -> no atomics.
__device__ float g_xf[2][Nn * 12];

// CSR incidence structure (built once per launch, ~18us):
//   g_off[n]..g_off[n+1] indexes g_ent; entry = {neighbor_id, bitcast(L0)}.
// Correction is symmetric in (src,dst) so no sign is stored.
__device__ int  g_off[Nn + 1];
__device__ int  g_cur[Nn];        // counts during hist, cursors during fill
__device__ int2 g_ent[2 * En];    // 12.8 MB

// ---------------------------------------------------------------------------
// Stage 1: x_pred = keypoints + tau * (hand_tokens @ head_w + head_b)
// One warp per point (b,n); coalesced float4 loads + shfl reduction.
// ---------------------------------------------------------------------------
__global__ __launch_bounds__(256) void predict_kernel(
    const float* __restrict__ kp, const float* __restrict__ ts,
    const float* __restrict__ ht, const float* __restrict__ hw,
    const float* __restrict__ hb)
{
    __shared__ float sw[Dn * 3];
    __shared__ float sb[3];
    int tid = threadIdx.x;
    for (int i = tid; i < Dn * 3; i += blockDim.x) sw[i] = hw[i];
    if (tid < 3) sb[tid] = hb[tid];
    __syncthreads();

    int warp = tid >> 5, lane = tid & 31;
    int p = blockIdx.x * 8 + warp;
    if (p >= NPTS) return;

    const float4* h = reinterpret_cast<const float4*>(ht + (size_t)p * Dn);
    float4 h0 = __ldg(&h[lane]);
    float4 h1 = __ldg(&h[32 + lane]);

    float a0 = 0.f, a1 = 0.f, a2 = 0.f;
    float hv[8] = {h0.x, h0.y, h0.z, h0.w, h1.x, h1.y, h1.z, h1.w};
    int   c0 = 4 * lane, c1 = 128 + 4 * lane;
    int   cc[8] = {c0, c0 + 1, c0 + 2, c0 + 3, c1, c1 + 1, c1 + 2, c1 + 3};
#pragma unroll
    for (int i = 0; i < 8; i++) {
        a0 = fmaf(hv[i], sw[cc[i] * 3 + 0], a0);
        a1 = fmaf(hv[i], sw[cc[i] * 3 + 1], a1);
        a2 = fmaf(hv[i], sw[cc[i] * 3 + 2], a2);
    }
#pragma unroll
    for (int o = 16; o >= 1; o >>= 1) {
        a0 += __shfl_xor_sync(0xffffffffu, a0, o);
        a1 += __shfl_xor_sync(0xffffffffu, a1, o);
        a2 += __shfl_xor_sync(0xffffffffu, a2, o);
    }
    if (lane == 0) {
        int b = p / Nn;
        int n = p - b * Nn;
        float tau = fmaxf(1.0f - __ldg(&ts[b]), 0.001f);
        float kx = __ldg(&kp[(size_t)p * 3 + 0]);
        float ky = __ldg(&kp[(size_t)p * 3 + 1]);
        float kz = __ldg(&kp[(size_t)p * 3 + 2]);
        int base = 12 * n + 3 * b;
        g_xf[0][base + 0] = fmaf(tau, a0 + sb[0], kx);
        g_xf[0][base + 1] = fmaf(tau, a1 + sb[1], ky);
        g_xf[0][base + 2] = fmaf(tau, a2 + sb[2], kz);
    }
}

// ---------------------------------------------------------------------------
// CSR build: zero -> histogram -> single-block scan -> fill
// ---------------------------------------------------------------------------
__global__ __launch_bounds__(256) void zero_kernel()
{
    int i = blockIdx.x * blockDim.x + threadIdx.x;
    if (i < Nn) g_cur[i] = 0;
}

__global__ __launch_bounds__(256) void hist_kernel(const int* __restrict__ ei)
{
    int e = blockIdx.x * blockDim.x + threadIdx.x;
    if (e >= En) return;
    atomicAdd(&g_cur[__ldg(&ei[e])], 1);
    atomicAdd(&g_cur[__ldg(&ei[En + e])], 1);
}

// Exclusive scan of g_cur[0..Nn) -> g_off, and reset g_cur = g_off (cursors).
// Single block of 1024 threads; each thread owns a contiguous chunk.
__global__ __launch_bounds__(1024) void scan_kernel()
{
    __shared__ int part[1024];
    const int T = 1024;
    const int chunk = (Nn + T - 1) / T;   // 49
    int t = threadIdx.x;
    int lo = t * chunk, hi = min(lo + chunk, Nn);

    int s = 0;
    for (int i = lo; i < hi; i++) s += g_cur[i];
    part[t] = s;
    __syncthreads();

    // Hillis-Steele inclusive scan over partials
    for (int o = 1; o < T; o <<= 1) {
        int v = (t >= o) ? part[t - o] : 0;
        __syncthreads();
        part[t] += v;
        __syncthreads();
    }
    int run = (t == 0) ? 0 : part[t - 1];   // exclusive prefix of this chunk

    for (int i = lo; i < hi; i++) {
        int c = g_cur[i];
        g_off[i] = run;
        g_cur[i] = run;    // cursor for fill
        run += c;
    }
    if (t == T - 1) g_off[Nn] = run;
}

__global__ __launch_bounds__(256) void fill_kernel(
    const int* __restrict__ ei, const float* __restrict__ rest)
{
    int e = blockIdx.x * blockDim.x + threadIdx.x;
    if (e >= En) return;
    int s = __ldg(&ei[e]);
    int d = __ldg(&ei[En + e]);
    int L0 = __float_as_int(__ldg(&rest[e]));
    int ps = atomicAdd(&g_cur[s], 1);
    g_ent[ps] = make_int2(d, L0);
    int pd = atomicAdd(&g_cur[d], 1);
    g_ent[pd] = make_int2(s, L0);
}

// ---------------------------------------------------------------------------
// One XPBD Jacobi iteration, node-centric: thread per node gathers all
// incident edges, recomputes corrections (symmetric formula), accumulates in
// registers, single coalesced 48B store. No atomics, no copy kernel.
// ---------------------------------------------------------------------------
__global__ __launch_bounds__(256) void node_kernel(int from, int to)
{
    int n = blockIdx.x * blockDim.x + threadIdx.x;
    if (n >= Nn) return;

    const float4* xin = reinterpret_cast<const float4*>(g_xf[from]);
    float4 o0 = __ldg(&xin[3 * n + 0]);
    float4 o1 = __ldg(&xin[3 * n + 1]);
    float4 o2 = __ldg(&xin[3 * n + 2]);
    float ox[4] = {o0.x, o0.w, o1.z, o2.y};
    float oy[4] = {o0.y, o1.x, o1.w, o2.z};
    float oz[4] = {o0.z, o1.y, o2.x, o2.w};

    float ax[4] = {0.f, 0.f, 0.f, 0.f};
    float ay[4] = {0.f, 0.f, 0.f, 0.f};
    float az[4] = {0.f, 0.f, 0.f, 0.f};

    int beg = __ldg(&g_off[n]);
    int end = __ldg(&g_off[n + 1]);

#pragma unroll 2
    for (int k = beg; k < end; k++) {
        int2  ent = __ldg(&g_ent[k]);
        int   j   = ent.x;
        float L0  = __int_as_float(ent.y);
        float4 j0 = __ldg(&xin[3 * j + 0]);
        float4 j1 = __ldg(&xin[3 * j + 1]);
        float4 j2 = __ldg(&xin[3 * j + 2]);
        float jx[4] = {j0.x, j0.w, j1.z, j2.y};
        float jy[4] = {j0.y, j1.x, j1.w, j2.z};
        float jz[4] = {j0.z, j1.y, j2.x, j2.w};
#pragma unroll
        for (int b = 0; b < Bn; b++) {
            float dx = ox[b] - jx[b];
            float dy = oy[b] - jy[b];
            float dz = oz[b] - jz[b];
            float d2 = fmaf(dx, dx, fmaf(dy, dy, dz * dz));
            float r  = rsqrtf(fmaxf(d2, 1e-24f));
            float sc = 0.5f * fmaf(L0, r, -1.0f);
            ax[b] += fminf(fmaxf(sc * dx, -0.15f), 0.15f);
            ay[b] += fminf(fmaxf(sc * dy, -0.15f), 0.15f);
            az[b] += fminf(fmaxf(sc * dz, -0.15f), 0.15f);
        }
    }

    float4* xout = reinterpret_cast<float4*>(g_xf[to]);
    xout[3 * n + 0] = make_float4(ox[0] + ax[0], oy[0] + ay[0],
                                  oz[0] + az[0], ox[1] + ax[1]);
    xout[3 * n + 1] = make_float4(oy[1] + ay[1], oz[1] + az[1],
                                  ox[2] + ax[2], oy[2] + ay[2]);
    xout[3 * n + 2] = make_float4(oz[2] + az[2], ox[3] + ax[3],
                                  oy[3] + ay[3], oz[3] + az[3]);
}

// ---------------------------------------------------------------------------
// Stage 3: v_eff = (x_corrected - keypoints) / tau
// ---------------------------------------------------------------------------
__global__ __launch_bounds__(256) void final_kernel(
    const float* __restrict__ kp, const float* __restrict__ ts,
    int buf, float* __restrict__ out)
{
    int n = blockIdx.x * blockDim.x + threadIdx.x;
    if (n >= Nn) return;
    const float4* x = reinterpret_cast<const float4*>(g_xf[buf]);
    float4 q0 = x[3 * n + 0];
    float4 q1 = x[3 * n + 1];
    float4 q2 = x[3 * n + 2];
    float px[4] = {q0.x, q0.w, q1.z, q2.y};
    float py[4] = {q0.y, q1.x, q1.w, q2.z};
    float pz[4] = {q0.z, q1.y, q2.x, q2.w};
#pragma unroll
    for (int b = 0; b < Bn; b++) {
        float inv_tau = 1.0f / fmaxf(1.0f - __ldg(&ts[b]), 0.001f);
        size_t o = (size_t)(b * Nn + n) * 3;
        out[o + 0] = (px[b] - __ldg(&kp[o + 0])) * inv_tau;
        out[o + 1] = (py[b] - __ldg(&kp[o + 1])) * inv_tau;
        out[o + 2] = (pz[b] - __ldg(&kp[o + 2])) * inv_tau;
    }
}

extern "C" void kernel_launch(void* const* d_in, const int* in_sizes, int n_in,
                              void* d_out, int out_size)
{
    const float* kp   = (const float*)d_in[0];  // keypoints   (B,N,3)
    const float* ts   = (const float*)d_in[1];  // timesteps   (B,)
    const float* ht   = (const float*)d_in[2];  // hand_tokens (B,N,D)
    const float* hw   = (const float*)d_in[3];  // head_w      (D,3)
    const float* hb   = (const float*)d_in[4];  // head_b      (3,)
    const int*   ei   = (const int*)  d_in[5];  // edge_index  (2,E)
    const float* rest = (const float*)d_in[6];  // rest_lengths(E,)
    float*       out  = (float*)d_out;          // v_eff       (B,N,3)

    (void)in_sizes; (void)n_in; (void)out_size;

    const int node_blocks = (Nn + 255) / 256;
    const int edge_blocks = (En + 255) / 256;

    // CSR build (independent of predict; overlaps nothing but is cheap)
    zero_kernel<<<node_blocks, 256>>>();
    hist_kernel<<<edge_blocks, 256>>>(ei);
    scan_kernel<<<1, 1024>>>();
    fill_kernel<<<edge_blocks, 256>>>(ei, rest);

    // Stage 1: prediction into buffer 0
    predict_kernel<<<NPTS / 8, 256>>>(kp, ts, ht, hw, hb);

    // Stage 2: 4 Jacobi XPBD iterations, node-centric, ping-pong
    node_kernel<<<node_blocks, 256>>>(0, 1);
    node_kernel<<<node_blocks, 256>>>(1, 0);
    node_kernel<<<node_blocks, 256>>>(0, 1);
    node_kernel<<<node_blocks, 256>>>(1, 0);

    // Stage 3: velocity output from buffer 0
    final_kernel<<<node_blocks, 256>>>(kp, ts, 0, out);
}

// round 5
// speedup vs baseline: 1.9074x; 1.9074x over previous
#include <cuda_runtime.h>
#include <cuda_bf16.h>

// Problem constants (fixed by the dataset)
#define Bn 4
#define Nn 50000
#define Dn 256
#define En 800000
#define NPTS (Bn * Nn)   // 200000
#define MAXDEG 96        // Poisson(32): P(deg>96) ~ 1e-18 over 50k nodes

// XPBD state, batch-interleaved: g_x[buf][4*n + b] = float4(x,y,z,pad) of
// node n, batch b. The 4 batches of a node are 64B contiguous, so the 4
// sibling threads (n,0..3) gather a neighbor with one fully-used 64B segment.
__device__ float4 g_x[2][NPTS];

// Fixed-slot incidence table (no scan needed): node n owns
// g_slot[n*MAXDEG .. n*MAXDEG+deg). entry = {neighbor, bitcast(L0)}.
// Correction formula is odd-symmetric in (src,dst), so no sign stored.
__device__ int  g_cnt[Nn];
__device__ int2 g_slot[Nn * MAXDEG];   // 38.4 MB

// ---------------------------------------------------------------------------
// Stage 1: x_pred = keypoints + tau * (hand_tokens @ head_w + head_b)
// One warp per point (b,n); coalesced float4 loads + shfl reduction.
// ---------------------------------------------------------------------------
__global__ __launch_bounds__(256) void predict_kernel(
    const float* __restrict__ kp, const float* __restrict__ ts,
    const float* __restrict__ ht, const float* __restrict__ hw,
    const float* __restrict__ hb)
{
    __shared__ float sw[Dn * 3];
    __shared__ float sb[3];
    int tid = threadIdx.x;
    for (int i = tid; i < Dn * 3; i += blockDim.x) sw[i] = hw[i];
    if (tid < 3) sb[tid] = hb[tid];
    __syncthreads();

    int warp = tid >> 5, lane = tid & 31;
    int p = blockIdx.x * 8 + warp;
    if (p >= NPTS) return;

    const float4* h = reinterpret_cast<const float4*>(ht + (size_t)p * Dn);
    float4 h0 = __ldg(&h[lane]);
    float4 h1 = __ldg(&h[32 + lane]);

    float a0 = 0.f, a1 = 0.f, a2 = 0.f;
    float hv[8] = {h0.x, h0.y, h0.z, h0.w, h1.x, h1.y, h1.z, h1.w};
    int   c0 = 4 * lane, c1 = 128 + 4 * lane;
    int   cc[8] = {c0, c0 + 1, c0 + 2, c0 + 3, c1, c1 + 1, c1 + 2, c1 + 3};
#pragma unroll
    for (int i = 0; i < 8; i++) {
        a0 = fmaf(hv[i], sw[cc[i] * 3 + 0], a0);
        a1 = fmaf(hv[i], sw[cc[i] * 3 + 1], a1);
        a2 = fmaf(hv[i], sw[cc[i] * 3 + 2], a2);
    }
#pragma unroll
    for (int o = 16; o >= 1; o >>= 1) {
        a0 += __shfl_xor_sync(0xffffffffu, a0, o);
        a1 += __shfl_xor_sync(0xffffffffu, a1, o);
        a2 += __shfl_xor_sync(0xffffffffu, a2, o);
    }
    if (lane == 0) {
        int b = p / Nn;
        int n = p - b * Nn;
        float tau = fmaxf(1.0f - __ldg(&ts[b]), 0.001f);
        float kx = __ldg(&kp[(size_t)p * 3 + 0]);
        float ky = __ldg(&kp[(size_t)p * 3 + 1]);
        float kz = __ldg(&kp[(size_t)p * 3 + 2]);
        g_x[0][4 * n + b] = make_float4(fmaf(tau, a0 + sb[0], kx),
                                        fmaf(tau, a1 + sb[1], ky),
                                        fmaf(tau, a2 + sb[2], kz), 0.0f);
    }
}

// ---------------------------------------------------------------------------
// Incidence build: zero cursors, then edge-parallel slotted fill.
// ---------------------------------------------------------------------------
__global__ __launch_bounds__(256) void zero_kernel()
{
    int i = blockIdx.x * blockDim.x + threadIdx.x;
    if (i < Nn) g_cnt[i] = 0;
}

__global__ __launch_bounds__(256) void fill_kernel(
    const int* __restrict__ ei, const float* __restrict__ rest)
{
    int e = blockIdx.x * blockDim.x + threadIdx.x;
    if (e >= En) return;
    int s  = __ldg(&ei[e]);
    int d  = __ldg(&ei[En + e]);
    int L0 = __float_as_int(__ldg(&rest[e]));
    int cs = atomicAdd(&g_cnt[s], 1);
    if (cs < MAXDEG) g_slot[s * MAXDEG + cs] = make_int2(d, L0);
    int cd = atomicAdd(&g_cnt[d], 1);
    if (cd < MAXDEG) g_slot[d * MAXDEG + cd] = make_int2(s, L0);
}

// ---------------------------------------------------------------------------
// One XPBD Jacobi iteration. Thread per (node, batch): 200k threads, no
// atomics, no copy. 4 sibling threads share entry loads (L1 broadcast) and
// their neighbor gathers form one contiguous 64B segment. Neighbors unrolled
// x4 with int4-paired entry loads for MLP.
// ---------------------------------------------------------------------------
__global__ __launch_bounds__(128) void node_kernel(int from, int to)
{
    int t = blockIdx.x * blockDim.x + threadIdx.x;
    if (t >= NPTS) return;
    int n = t >> 2;
    int b = t & 3;

    const float4* __restrict__ xin = g_x[from];
    float4 own = __ldg(&xin[t]);

    int deg = min(__ldg(&g_cnt[n]), MAXDEG);
    const int2* row = &g_slot[n * MAXDEG];

    float ax = 0.f, ay = 0.f, az = 0.f;

    for (int k = 0; k < deg; k += 4) {
        // entries k..k+3 (2 x int4; row is 16B-aligned, k multiple of 4)
        int4 ea = __ldg(reinterpret_cast<const int4*>(row + k));
        int4 eb = __ldg(reinterpret_cast<const int4*>(row + k + 2));
        int   js[4]  = {ea.x, ea.z, eb.x, eb.z};
        float L0s[4] = {__int_as_float(ea.y), __int_as_float(ea.w),
                        __int_as_float(eb.y), __int_as_float(eb.w)};
        float4 xj[4];
#pragma unroll
        for (int i = 0; i < 4; i++)
            xj[i] = __ldg(&xin[4 * js[i] + b]);
#pragma unroll
        for (int i = 0; i < 4; i++) {
            float dx = own.x - xj[i].x;
            float dy = own.y - xj[i].y;
            float dz = own.z - xj[i].z;
            float d2 = fmaf(dx, dx, fmaf(dy, dy, dz * dz));
            float r  = rsqrtf(fmaxf(d2, 1e-24f));
            float sc = 0.5f * fmaf(L0s[i], r, -1.0f);
            sc = (k + i < deg) ? sc : 0.0f;   // mask tail-group padding
            ax += fminf(fmaxf(sc * dx, -0.15f), 0.15f);
            ay += fminf(fmaxf(sc * dy, -0.15f), 0.15f);
            az += fminf(fmaxf(sc * dz, -0.15f), 0.15f);
        }
    }

    g_x[to][t] = make_float4(own.x + ax, own.y + ay, own.z + az, 0.0f);
}

// ---------------------------------------------------------------------------
// Stage 3: v_eff = (x_corrected - keypoints) / tau
// Thread per node: 64B contiguous state read, per-batch writes.
// ---------------------------------------------------------------------------
__global__ __launch_bounds__(256) void final_kernel(
    const float* __restrict__ kp, const float* __restrict__ ts,
    int buf, float* __restrict__ out)
{
    int n = blockIdx.x * blockDim.x + threadIdx.x;
    if (n >= Nn) return;
    const float4* x = g_x[buf];
#pragma unroll
    for (int b = 0; b < Bn; b++) {
        float4 p = x[4 * n + b];
        float inv_tau = 1.0f / fmaxf(1.0f - __ldg(&ts[b]), 0.001f);
        size_t o = (size_t)(b * Nn + n) * 3;
        out[o + 0] = (p.x - __ldg(&kp[o + 0])) * inv_tau;
        out[o + 1] = (p.y - __ldg(&kp[o + 1])) * inv_tau;
        out[o + 2] = (p.z - __ldg(&kp[o + 2])) * inv_tau;
    }
}

extern "C" void kernel_launch(void* const* d_in, const int* in_sizes, int n_in,
                              void* d_out, int out_size)
{
    const float* kp   = (const float*)d_in[0];  // keypoints   (B,N,3)
    const float* ts   = (const float*)d_in[1];  // timesteps   (B,)
    const float* ht   = (const float*)d_in[2];  // hand_tokens (B,N,D)
    const float* hw   = (const float*)d_in[3];  // head_w      (D,3)
    const float* hb   = (const float*)d_in[4];  // head_b      (3,)
    const int*   ei   = (const int*)  d_in[5];  // edge_index  (2,E)
    const float* rest = (const float*)d_in[6];  // rest_lengths(E,)
    float*       out  = (float*)d_out;          // v_eff       (B,N,3)

    (void)in_sizes; (void)n_in; (void)out_size;

    const int nb_nodes = (Nn + 255) / 256;
    const int nb_edges = (En + 255) / 256;
    const int nb_nodeb = (NPTS + 127) / 128;

    // Incidence build (zero + slotted fill; no scan)
    zero_kernel<<<nb_nodes, 256>>>();
    fill_kernel<<<nb_edges, 256>>>(ei, rest);

    // Stage 1: prediction into buffer 0
    predict_kernel<<<NPTS / 8, 256>>>(kp, ts, ht, hw, hb);

    // Stage 2: 4 Jacobi XPBD iterations, node-centric, ping-pong
    node_kernel<<<nb_nodeb, 128>>>(0, 1);
    node_kernel<<<nb_nodeb, 128>>>(1, 0);
    node_kernel<<<nb_nodeb, 128>>>(0, 1);
    node_kernel<<<nb_nodeb, 128>>>(1, 0);

    // Stage 3: velocity output from buffer 0
    final_kernel<<<nb_nodes, 256>>>(kp, ts, 0, out);
}

// round 6
// speedup vs baseline: 1.9264x; 1.0100x over previous
#include <cuda_runtime.h>
#include <cuda_bf16.h>

// Problem constants (fixed by the dataset)
#define Bn 4
#define Nn 50000
#define Dn 256
#define En 800000
#define NPTS (Bn * Nn)   // 200000
#define MAXDEG 96        // Poisson(32): P(deg>96) ~ 1e-18 over 50k nodes

// XPBD state, batch-interleaved: g_x[buf][4*n + b] = float4(x,y,z,pad) of
// node n, batch b. The 4 batches of a node are 64B contiguous, so the 4
// sibling threads (n,0..3) gather a neighbor with one fully-used 64B segment.
__device__ float4 g_x[2][NPTS];

// Fixed-slot incidence table: node n owns g_slot[n*MAXDEG .. n*MAXDEG+deg).
// entry = {neighbor, bitcast(L0)}. Rows padded to a multiple of 4 with
// self-edges {n, 1.0} whose correction is exactly 0 (dx=dy=dz=0).
__device__ int  g_cnt[Nn];
__device__ int2 g_slot[Nn * MAXDEG];   // 38.4 MB

// ---------------------------------------------------------------------------
// Stage 1: x_pred = keypoints + tau * (hand_tokens @ head_w + head_b)
// One warp per point (b,n); coalesced float4 loads + shfl reduction.
// ---------------------------------------------------------------------------
__global__ __launch_bounds__(256) void predict_kernel(
    const float* __restrict__ kp, const float* __restrict__ ts,
    const float* __restrict__ ht, const float* __restrict__ hw,
    const float* __restrict__ hb)
{
    __shared__ float sw[Dn * 3];
    __shared__ float sb[3];
    int tid = threadIdx.x;
    for (int i = tid; i < Dn * 3; i += blockDim.x) sw[i] = hw[i];
    if (tid < 3) sb[tid] = hb[tid];
    __syncthreads();

    int warp = tid >> 5, lane = tid & 31;
    int p = blockIdx.x * 8 + warp;
    if (p >= NPTS) return;

    const float4* h = reinterpret_cast<const float4*>(ht + (size_t)p * Dn);
    float4 h0 = __ldg(&h[lane]);
    float4 h1 = __ldg(&h[32 + lane]);

    float a0 = 0.f, a1 = 0.f, a2 = 0.f;
    float hv[8] = {h0.x, h0.y, h0.z, h0.w, h1.x, h1.y, h1.z, h1.w};
    int   c0 = 4 * lane, c1 = 128 + 4 * lane;
    int   cc[8] = {c0, c0 + 1, c0 + 2, c0 + 3, c1, c1 + 1, c1 + 2, c1 + 3};
#pragma unroll
    for (int i = 0; i < 8; i++) {
        a0 = fmaf(hv[i], sw[cc[i] * 3 + 0], a0);
        a1 = fmaf(hv[i], sw[cc[i] * 3 + 1], a1);
        a2 = fmaf(hv[i], sw[cc[i] * 3 + 2], a2);
    }
#pragma unroll
    for (int o = 16; o >= 1; o >>= 1) {
        a0 += __shfl_xor_sync(0xffffffffu, a0, o);
        a1 += __shfl_xor_sync(0xffffffffu, a1, o);
        a2 += __shfl_xor_sync(0xffffffffu, a2, o);
    }
    if (lane == 0) {
        int b = p / Nn;
        int n = p - b * Nn;
        float tau = fmaxf(1.0f - __ldg(&ts[b]), 0.001f);
        float kx = __ldg(&kp[(size_t)p * 3 + 0]);
        float ky = __ldg(&kp[(size_t)p * 3 + 1]);
        float kz = __ldg(&kp[(size_t)p * 3 + 2]);
        g_x[0][4 * n + b] = make_float4(fmaf(tau, a0 + sb[0], kx),
                                        fmaf(tau, a1 + sb[1], ky),
                                        fmaf(tau, a2 + sb[2], kz), 0.0f);
    }
}

// ---------------------------------------------------------------------------
// Incidence build: zero cursors -> edge-parallel slotted fill -> pad rows to
// a multiple of 4 with zero-contribution self-edges. Runs on a side stream,
// fully hidden under the (DRAM-bound) predict kernel.
// ---------------------------------------------------------------------------
__global__ __launch_bounds__(256) void zero_kernel()
{
    int i = blockIdx.x * blockDim.x + threadIdx.x;
    if (i < Nn) g_cnt[i] = 0;
}

__global__ __launch_bounds__(256) void fill_kernel(
    const int* __restrict__ ei, const float* __restrict__ rest)
{
    int e = blockIdx.x * blockDim.x + threadIdx.x;
    if (e >= En) return;
    int s  = __ldg(&ei[e]);
    int d  = __ldg(&ei[En + e]);
    int L0 = __float_as_int(__ldg(&rest[e]));
    int cs = atomicAdd(&g_cnt[s], 1);
    if (cs < MAXDEG) g_slot[s * MAXDEG + cs] = make_int2(d, L0);
    int cd = atomicAdd(&g_cnt[d], 1);
    if (cd < MAXDEG) g_slot[d * MAXDEG + cd] = make_int2(s, L0);
}

__global__ __launch_bounds__(256) void pad_kernel()
{
    int n = blockIdx.x * blockDim.x + threadIdx.x;
    if (n >= Nn) return;
    int c = min(g_cnt[n], MAXDEG);
    int p = (c + 3) & ~3;                    // pad to multiple of 4
    int2 self = make_int2(n, __float_as_int(1.0f));
    for (int k = c; k < p; k++) g_slot[n * MAXDEG + k] = self;
    g_cnt[n] = p;
}

// ---------------------------------------------------------------------------
// One XPBD Jacobi iteration. Thread per (node, batch): 200k threads, no
// atomics, no copy, no tail masking (rows are 4-padded). 4 sibling threads
// share entry loads (L1 broadcast); their neighbor gathers form contiguous
// 64B segments. Neighbors unrolled x4 with int4-paired entry loads for MLP.
// ---------------------------------------------------------------------------
__global__ __launch_bounds__(128) void node_kernel(int from, int to)
{
    int t = blockIdx.x * blockDim.x + threadIdx.x;
    if (t >= NPTS) return;
    int n = t >> 2;
    int b = t & 3;

    const float4* __restrict__ xin = g_x[from];
    float4 own = __ldg(&xin[t]);

    int deg = __ldg(&g_cnt[n]);              // multiple of 4
    const int2* row = &g_slot[n * MAXDEG];

    float ax = 0.f, ay = 0.f, az = 0.f;

    for (int k = 0; k < deg; k += 4) {
        int4 ea = __ldg(reinterpret_cast<const int4*>(row + k));
        int4 eb = __ldg(reinterpret_cast<const int4*>(row + k + 2));
        int   js[4]  = {ea.x, ea.z, eb.x, eb.z};
        float L0s[4] = {__int_as_float(ea.y), __int_as_float(ea.w),
                        __int_as_float(eb.y), __int_as_float(eb.w)};
        float4 xj[4];
#pragma unroll
        for (int i = 0; i < 4; i++)
            xj[i] = __ldg(&xin[4 * js[i] + b]);
#pragma unroll
        for (int i = 0; i < 4; i++) {
            float dx = own.x - xj[i].x;
            float dy = own.y - xj[i].y;
            float dz = own.z - xj[i].z;
            float d2 = fmaf(dx, dx, fmaf(dy, dy, dz * dz));
            float r  = rsqrtf(fmaxf(d2, 1e-24f));
            float sc = 0.5f * fmaf(L0s[i], r, -1.0f);
            ax += fminf(fmaxf(sc * dx, -0.15f), 0.15f);
            ay += fminf(fmaxf(sc * dy, -0.15f), 0.15f);
            az += fminf(fmaxf(sc * dz, -0.15f), 0.15f);
        }
    }

    g_x[to][t] = make_float4(own.x + ax, own.y + ay, own.z + az, 0.0f);
}

// ---------------------------------------------------------------------------
// Stage 3: v_eff = (x_corrected - keypoints) / tau
// ---------------------------------------------------------------------------
__global__ __launch_bounds__(256) void final_kernel(
    const float* __restrict__ kp, const float* __restrict__ ts,
    int buf, float* __restrict__ out)
{
    int n = blockIdx.x * blockDim.x + threadIdx.x;
    if (n >= Nn) return;
    const float4* x = g_x[buf];
#pragma unroll
    for (int b = 0; b < Bn; b++) {
        float4 p = x[4 * n + b];
        float inv_tau = 1.0f / fmaxf(1.0f - __ldg(&ts[b]), 0.001f);
        size_t o = (size_t)(b * Nn + n) * 3;
        out[o + 0] = (p.x - __ldg(&kp[o + 0])) * inv_tau;
        out[o + 1] = (p.y - __ldg(&kp[o + 1])) * inv_tau;
        out[o + 2] = (p.z - __ldg(&kp[o + 2])) * inv_tau;
    }
}

extern "C" void kernel_launch(void* const* d_in, const int* in_sizes, int n_in,
                              void* d_out, int out_size)
{
    const float* kp   = (const float*)d_in[0];  // keypoints   (B,N,3)
    const float* ts   = (const float*)d_in[1];  // timesteps   (B,)
    const float* ht   = (const float*)d_in[2];  // hand_tokens (B,N,D)
    const float* hw   = (const float*)d_in[3];  // head_w      (D,3)
    const float* hb   = (const float*)d_in[4];  // head_b      (3,)
    const int*   ei   = (const int*)  d_in[5];  // edge_index  (2,E)
    const float* rest = (const float*)d_in[6];  // rest_lengths(E,)
    float*       out  = (float*)d_out;          // v_eff       (B,N,3)

    (void)in_sizes; (void)n_in; (void)out_size;

    // Side stream + fork/join events, created once on the first call (the
    // correctness run, which is not under capture). Host-side objects only —
    // no device memory. The fork/join below is the documented pattern for
    // multi-stream work inside stream capture.
    static cudaStream_t side = nullptr;
    static cudaEvent_t  ev_fork = nullptr, ev_join = nullptr;
    if (side == nullptr) {
        cudaStreamCreateWithFlags(&side, cudaStreamNonBlocking);
        cudaEventCreateWithFlags(&ev_fork, cudaEventDisableTiming);
        cudaEventCreateWithFlags(&ev_join, cudaEventDisableTiming);
    }

    const int nb_nodes = (Nn + 255) / 256;
    const int nb_edges = (En + 255) / 256;
    const int nb_nodeb = (NPTS + 127) / 128;

    // Fork: incidence build on side stream, concurrent with predict (which is
    // HBM-bound while the build is LTS/atomic-bound — disjoint resources).
    cudaEventRecord(ev_fork, 0);
    cudaStreamWaitEvent(side, ev_fork, 0);
    zero_kernel<<<nb_nodes, 256, 0, side>>>();
    fill_kernel<<<nb_edges, 256, 0, side>>>(ei, rest);
    pad_kernel <<<nb_nodes, 256, 0, side>>>();

    // Stage 1 on the main stream, overlapping the build
    predict_kernel<<<NPTS / 8, 256>>>(kp, ts, ht, hw, hb);

    // Join
    cudaEventRecord(ev_join, side);
    cudaStreamWaitEvent(0, ev_join, 0);

    // Stage 2: 4 Jacobi XPBD iterations, node-centric, ping-pong
    node_kernel<<<nb_nodeb, 128>>>(0, 1);
    node_kernel<<<nb_nodeb, 128>>>(1, 0);
    node_kernel<<<nb_nodeb, 128>>>(0, 1);
    node_kernel<<<nb_nodeb, 128>>>(1, 0);

    // Stage 3: velocity output from buffer 0
    final_kernel<<<nb_nodes, 256>>>(kp, ts, 0, out);
}